// round 2
// baseline (speedup 1.0000x reference)
#include <cuda_runtime.h>
#include <math.h>

#define NN 50000
#define NE 1600000
#define FIN 128
#define HID 160
#define NG 512
#define NC 2
#define BN_EPS 1e-5f

// ---------------- scratch (static __device__, no allocs) ----------------
__device__ float g_hs[NN * HID];     // scaled linear output (gather source)
__device__ float g_feat[NN * HID];   // layer output features
__device__ float g_inv[NN];          // 1/sqrt(deg)
__device__ int   g_indeg[NN];
__device__ int   g_rowptr[NN + 1];
__device__ int   g_cursor[NN];
__device__ int   g_colidx[NE];
__device__ int   g_bsums[256];
__device__ int   g_gcnt[NG];
__device__ int   g_goff[NG + 1];
__device__ float g_pooled[NG * HID];

// ---------------- init ----------------
__global__ void k_init() {
    int i = blockIdx.x * blockDim.x + threadIdx.x;
    if (i < NN) g_indeg[i] = 0;
    if (i < NG) g_gcnt[i] = 0;
}

__global__ void k_count(const int* __restrict__ dst) {
    for (int e = blockIdx.x * blockDim.x + threadIdx.x; e < NE; e += gridDim.x * blockDim.x)
        atomicAdd(&g_indeg[dst[e]], 1);
}

__global__ void k_gcount(const int* __restrict__ batch) {
    int i = blockIdx.x * blockDim.x + threadIdx.x;
    if (i < NN) atomicAdd(&g_gcnt[batch[i]], 1);
}

// ---------------- exclusive scan of indeg -> rowptr ----------------
__global__ void k_scan1() {   // grid: 98 blocks x 512
    __shared__ int sh[512];
    int i = blockIdx.x * 512 + threadIdx.x;
    int v = (i < NN) ? g_indeg[i] : 0;
    sh[threadIdx.x] = v;
    __syncthreads();
    for (int off = 1; off < 512; off <<= 1) {
        int t = (threadIdx.x >= off) ? sh[threadIdx.x - off] : 0;
        __syncthreads();
        sh[threadIdx.x] += t;
        __syncthreads();
    }
    if (i < NN) g_rowptr[i] = sh[threadIdx.x] - v;  // exclusive within block
    if (threadIdx.x == 511) g_bsums[blockIdx.x] = sh[511];
}

__global__ void k_scan2(int nb) {  // 1 thread: scan block sums
    if (threadIdx.x == 0 && blockIdx.x == 0) {
        int acc = 0;
        for (int b = 0; b < nb; b++) { int t = g_bsums[b]; g_bsums[b] = acc; acc += t; }
    }
}

__global__ void k_scan3() {
    int i = blockIdx.x * blockDim.x + threadIdx.x;
    if (i < NN) {
        int r = g_rowptr[i] + g_bsums[i >> 9];
        g_rowptr[i] = r;
        g_cursor[i] = r;
        g_inv[i] = rsqrtf((float)g_indeg[i] + 1.0f);   // deg = indeg + self loop
    }
    if (i == 0) g_rowptr[NN] = NE;
}

__global__ void k_gscan() {   // 1 block x 512: exclusive scan of graph counts
    __shared__ int sh[512];
    int x = threadIdx.x;
    int v = g_gcnt[x];
    sh[x] = v;
    __syncthreads();
    for (int off = 1; off < 512; off <<= 1) {
        int t = (x >= off) ? sh[x - off] : 0;
        __syncthreads();
        sh[x] += t;
        __syncthreads();
    }
    g_goff[x] = sh[x] - v;
    if (x == 511) g_goff[NG] = sh[511];
}

__global__ void k_scatter(const int* __restrict__ src, const int* __restrict__ dst) {
    for (int e = blockIdx.x * blockDim.x + threadIdx.x; e < NE; e += gridDim.x * blockDim.x) {
        int p = atomicAdd(&g_cursor[dst[e]], 1);
        g_colidx[p] = src[e];
    }
}

// ---------------- GEMM: g_hs = (X @ W) * inv[row]  (no bias here) ----------------
// X: [M,K] row-major, W: [K,HID] row-major. Block tile 64 x 160, threads 256 (16x16),
// per-thread 4x10 register tile.
__global__ __launch_bounds__(256) void k_gemm(const float* __restrict__ X,
                                              const float* __restrict__ W,
                                              int M, int K) {
    __shared__ float As[64][33];
    __shared__ float Bs[32][HID];
    int tx = threadIdx.x & 15;
    int ty = threadIdx.x >> 4;
    int rowBase = blockIdx.x * 64;

    float acc[4][10];
#pragma unroll
    for (int r = 0; r < 4; r++)
#pragma unroll
        for (int c = 0; c < 10; c++) acc[r][c] = 0.f;

    for (int k0 = 0; k0 < K; k0 += 32) {
        for (int idx = threadIdx.x; idx < 64 * 32; idx += 256) {
            int r = idx >> 5, k = idx & 31;
            int gr = rowBase + r;
            As[r][k] = (gr < M) ? X[(size_t)gr * K + k0 + k] : 0.f;
        }
        for (int idx = threadIdx.x; idx < 32 * HID; idx += 256) {
            int k = idx / HID, c = idx % HID;
            Bs[k][c] = W[(size_t)(k0 + k) * HID + c];
        }
        __syncthreads();
#pragma unroll
        for (int kk = 0; kk < 32; kk++) {
            float a[4], b[10];
#pragma unroll
            for (int r = 0; r < 4; r++) a[r] = As[ty + 16 * r][kk];
#pragma unroll
            for (int c = 0; c < 10; c++) b[c] = Bs[kk][tx + 16 * c];
#pragma unroll
            for (int r = 0; r < 4; r++)
#pragma unroll
                for (int c = 0; c < 10; c++) acc[r][c] = fmaf(a[r], b[c], acc[r][c]);
        }
        __syncthreads();
    }
#pragma unroll
    for (int r = 0; r < 4; r++) {
        int gr = rowBase + ty + 16 * r;
        if (gr < M) {
            float s = g_inv[gr];
#pragma unroll
            for (int c = 0; c < 10; c++)
                g_hs[(size_t)gr * HID + tx + 16 * c] = acc[r][c] * s;
        }
    }
}

// ---------------- Aggregate + bias + BN + ReLU ----------------
// out[d] = relu( BN( inv[d]*(hs[d] + sum_{s in in(d)} hs[s]) + bias ) )
__global__ __launch_bounds__(256) void k_agg(const float* __restrict__ bias,
                                             const float* __restrict__ gam,
                                             const float* __restrict__ bet,
                                             const float* __restrict__ mean,
                                             const float* __restrict__ var) {
    int warp = (blockIdx.x * blockDim.x + threadIdx.x) >> 5;
    int lane = threadIdx.x & 31;
    if (warp >= NN) return;
    int d = warp;

    float acc[5];
    const float* hr = g_hs + (size_t)d * HID;
#pragma unroll
    for (int j = 0; j < 5; j++) acc[j] = hr[lane + 32 * j];   // self loop term

    int beg = g_rowptr[d], end = g_rowptr[d + 1];
    for (int e0 = beg; e0 < end; e0 += 32) {
        int n = min(32, end - e0);
        int myidx = (lane < n) ? g_colidx[e0 + lane] : 0;
        for (int t = 0; t < n; t++) {
            int s = __shfl_sync(0xffffffffu, myidx, t);
            const float* r = g_hs + (size_t)s * HID;
#pragma unroll
            for (int j = 0; j < 5; j++) acc[j] += r[lane + 32 * j];
        }
    }

    float idv = g_inv[d];
#pragma unroll
    for (int j = 0; j < 5; j++) {
        int c = lane + 32 * j;
        float A = gam[c] * rsqrtf(var[c] + BN_EPS);
        float y = (acc[j] * idv + bias[c] - mean[c]) * A + bet[c];
        g_feat[(size_t)d * HID + c] = fmaxf(y, 0.f);
    }
}

// ---------------- mean pool per graph ----------------
__global__ void k_pool() {   // grid: NG blocks x HID threads
    int g = blockIdx.x;
    int c = threadIdx.x;
    int s0 = g_goff[g];
    int cnt = g_goff[g + 1] - s0;
    float s = 0.f;
    for (int i = 0; i < cnt; i++) s += g_feat[(size_t)(s0 + i) * HID + c];
    g_pooled[g * HID + c] = s / fmaxf((float)cnt, 1.f);
}

// ---------------- MLP head ----------------
__global__ void k_head(const float* __restrict__ Wc1, const float* __restrict__ bc1,
                       const float* __restrict__ Wc2, const float* __restrict__ bc2,
                       float* __restrict__ out) {   // grid: NG blocks x 80 threads
    __shared__ float p[HID];
    __shared__ float z[80];
    int g = blockIdx.x;
    int j = threadIdx.x;
    p[j] = g_pooled[g * HID + j];
    p[j + 80] = g_pooled[g * HID + j + 80];
    __syncthreads();
    float s = bc1[j];
    for (int i = 0; i < HID; i++) s = fmaf(p[i], Wc1[i * 80 + j], s);
    z[j] = fmaxf(s, 0.f);
    __syncthreads();
    if (j < NC) {
        float o = bc2[j];
        for (int i = 0; i < 80; i++) o = fmaf(z[i], Wc2[i * NC + j], o);
        out[g * NC + j] = o;
    }
}

// ---------------- launch ----------------
extern "C" void kernel_launch(void* const* d_in, const int* in_sizes, int n_in,
                              void* d_out, int out_size) {
    const float* x   = (const float*)d_in[0];
    const int* ei    = (const int*)d_in[1];
    const int* batch = (const int*)d_in[2];
    const float* W1  = (const float*)d_in[3];
    const float* b1  = (const float*)d_in[4];
    const float* W2  = (const float*)d_in[5];
    const float* b2  = (const float*)d_in[6];
    const float* W3  = (const float*)d_in[7];
    const float* b3  = (const float*)d_in[8];
    const float* g1  = (const float*)d_in[9];
    const float* be1 = (const float*)d_in[10];
    const float* m1  = (const float*)d_in[11];
    const float* v1  = (const float*)d_in[12];
    const float* g2  = (const float*)d_in[13];
    const float* be2 = (const float*)d_in[14];
    const float* m2  = (const float*)d_in[15];
    const float* v2  = (const float*)d_in[16];
    const float* g3  = (const float*)d_in[17];
    const float* be3 = (const float*)d_in[18];
    const float* m3  = (const float*)d_in[19];
    const float* v3  = (const float*)d_in[20];
    const float* Wc1 = (const float*)d_in[21];
    const float* bc1 = (const float*)d_in[22];
    const float* Wc2 = (const float*)d_in[23];
    const float* bc2 = (const float*)d_in[24];
    const int* src = ei;
    const int* dst = ei + NE;
    float* out = (float*)d_out;

    float* feat_ptr = nullptr;
    cudaGetSymbolAddress((void**)&feat_ptr, g_feat);

    // ---- graph structure (rebuilt each call; deterministic work) ----
    k_init<<<(NN + 255) / 256, 256>>>();
    k_count<<<2048, 256>>>(dst);
    k_gcount<<<(NN + 255) / 256, 256>>>(batch);
    k_scan1<<<(NN + 511) / 512, 512>>>();
    k_scan2<<<1, 32>>>((NN + 511) / 512);
    k_scan3<<<(NN + 255) / 256, 256>>>();
    k_gscan<<<1, 512>>>();
    k_scatter<<<2048, 256>>>(src, dst);

    const int gemm_blocks = (NN + 63) / 64;
    const int agg_blocks = (NN + 7) / 8;   // 8 warps per 256-thread block

    // layer 1
    k_gemm<<<gemm_blocks, 256>>>(x, W1, NN, FIN);
    k_agg<<<agg_blocks, 256>>>(b1, g1, be1, m1, v1);
    // layer 2
    k_gemm<<<gemm_blocks, 256>>>(feat_ptr, W2, NN, HID);
    k_agg<<<agg_blocks, 256>>>(b2, g2, be2, m2, v2);
    // layer 3
    k_gemm<<<gemm_blocks, 256>>>(feat_ptr, W3, NN, HID);
    k_agg<<<agg_blocks, 256>>>(b3, g3, be3, m3, v3);

    // pool + head
    k_pool<<<NG, HID>>>();
    k_head<<<NG, 80>>>(Wc1, bc1, Wc2, bc2, out);
}

// round 3
// speedup vs baseline: 1.1667x; 1.1667x over previous
#include <cuda_runtime.h>
#include <math.h>

#define NN 50000
#define NE 1600000
#define FIN 128
#define HID 160
#define NG 512
#define NC 2
#define BN_EPS 1e-5f

// ---------------- scratch (static __device__, no allocs) ----------------
__device__ __align__(16) float g_hs[NN * HID];     // scaled linear output (gather source)
__device__ __align__(16) float g_feat[NN * HID];   // layer output features
__device__ float g_inv[NN];                        // 1/sqrt(deg)
__device__ int   g_indeg[NN];
__device__ int   g_rowptr[NN + 1];
__device__ int   g_cursor[NN];
__device__ int   g_colidx[NE];
__device__ int   g_bsums[128];
__device__ int   g_gcnt[NG];
__device__ int   g_goff[NG + 1];
__device__ float g_pooled[NG * HID];

// ---------------- f32x2 helpers ----------------
__device__ __forceinline__ unsigned long long f2_fma(unsigned long long a,
                                                     unsigned long long b,
                                                     unsigned long long c) {
    unsigned long long d;
    asm("fma.rn.f32x2 %0, %1, %2, %3;" : "=l"(d) : "l"(a), "l"(b), "l"(c));
    return d;
}
__device__ __forceinline__ unsigned long long f2_add(unsigned long long a,
                                                     unsigned long long b) {
    unsigned long long d;
    asm("add.rn.f32x2 %0, %1, %2;" : "=l"(d) : "l"(a), "l"(b));
    return d;
}
__device__ __forceinline__ unsigned long long f2_dup(float a) {
    unsigned long long d;
    asm("mov.b64 %0, {%1, %1};" : "=l"(d) : "f"(a));
    return d;
}
union F2U { float2 f2; unsigned long long u; };

__device__ __forceinline__ unsigned long long ld2(const float* p) {
    F2U t; t.f2 = *reinterpret_cast<const float2*>(p); return t.u;
}

// ---------------- build: count indeg + graph-node counts ----------------
__global__ void k_count2(const int* __restrict__ dst, const int* __restrict__ batch) {
    int stride = gridDim.x * blockDim.x;
    int t0 = blockIdx.x * blockDim.x + threadIdx.x;
    for (int e = t0; e < NE; e += stride)
        atomicAdd(&g_indeg[dst[e]], 1);
    for (int i = t0; i < NN; i += stride)
        atomicAdd(&g_gcnt[batch[i]], 1);
}

// ---------------- exclusive scan of indeg -> rowptr (pass 1) ----------------
__global__ void k_scan1() {   // grid: 98 blocks x 512
    __shared__ int sh[512];
    int i = blockIdx.x * 512 + threadIdx.x;
    int v = (i < NN) ? g_indeg[i] : 0;
    sh[threadIdx.x] = v;
    __syncthreads();
    for (int off = 1; off < 512; off <<= 1) {
        int t = (threadIdx.x >= off) ? sh[threadIdx.x - off] : 0;
        __syncthreads();
        sh[threadIdx.x] += t;
        __syncthreads();
    }
    if (i < NN) g_rowptr[i] = sh[threadIdx.x] - v;  // exclusive within block
    if (threadIdx.x == 511) g_bsums[blockIdx.x] = sh[511];
}

// ---------------- block-sums scan (parallel) + graph-offset scan ----------------
__global__ void k_scan2g(int nb) {   // 1 block x 512
    __shared__ int sb[128];
    __shared__ int sg[512];
    int x = threadIdx.x;
    // scan of block sums (nb <= 128) by first 128 threads
    int vb = 0;
    if (x < 128) { vb = (x < nb) ? g_bsums[x] : 0; sb[x] = vb; }
    __syncthreads();
    for (int off = 1; off < 128; off <<= 1) {
        int t = (x < 128 && x >= off) ? sb[x - off] : 0;
        __syncthreads();
        if (x < 128) sb[x] += t;
        __syncthreads();
    }
    if (x < nb) g_bsums[x] = sb[x] - vb;   // exclusive
    // scan of graph counts (512)
    int vg = g_gcnt[x];
    sg[x] = vg;
    __syncthreads();
    for (int off = 1; off < 512; off <<= 1) {
        int t = (x >= off) ? sg[x - off] : 0;
        __syncthreads();
        sg[x] += t;
        __syncthreads();
    }
    g_goff[x] = sg[x] - vg;
    if (x == 511) g_goff[NG] = sg[511];
}

__global__ void k_scan3() {
    int i = blockIdx.x * blockDim.x + threadIdx.x;
    if (i < NN) {
        int r = g_rowptr[i] + g_bsums[i >> 9];
        g_rowptr[i] = r;
        g_cursor[i] = r;
        g_inv[i] = rsqrtf((float)g_indeg[i] + 1.0f);   // deg = indeg + self loop
    }
    if (i == 0) g_rowptr[NN] = NE;
}

__global__ void k_scatter(const int* __restrict__ src, const int* __restrict__ dst) {
    for (int e = blockIdx.x * blockDim.x + threadIdx.x; e < NE; e += gridDim.x * blockDim.x) {
        int p = atomicAdd(&g_cursor[dst[e]], 1);
        g_colidx[p] = src[e];
    }
}

// ---------------- GEMM: g_hs = (X @ W) * inv[row] ----------------
// X: [M,K] row-major, W: [K,160] row-major. Block tile 128 x 160, 256 threads,
// per-thread 8 rows x 5 col-pairs, packed f32x2 FMA.
__global__ __launch_bounds__(256) void k_gemm(const float* __restrict__ X,
                                              const float* __restrict__ W,
                                              int M, int K) {
    __shared__ __align__(16) float As[32][128];   // k-major: [k][row]
    __shared__ __align__(16) float Bs[32][160];   // [k][col]
    const int tid = threadIdx.x;
    const int tx = tid & 15;
    const int ty = tid >> 4;
    const int rowBase = blockIdx.x * 128;

    unsigned long long acc[8][5];
#pragma unroll
    for (int q = 0; q < 8; q++)
#pragma unroll
        for (int p = 0; p < 5; p++) acc[q][p] = 0ull;

    for (int k0 = 0; k0 < K; k0 += 32) {
        // load A tile (transposed into smem)
#pragma unroll
        for (int i = 0; i < 4; i++) {
            int idx = tid + i * 256;          // < 1024
            int row = idx & 127;
            int k = (idx >> 7) << 2;          // 0,4,...,28
            int gr = rowBase + row;
            float4 v = make_float4(0.f, 0.f, 0.f, 0.f);
            if (gr < M) v = *reinterpret_cast<const float4*>(X + (size_t)gr * K + k0 + k);
            As[k + 0][row] = v.x;
            As[k + 1][row] = v.y;
            As[k + 2][row] = v.z;
            As[k + 3][row] = v.w;
        }
        // load B tile
#pragma unroll
        for (int i = 0; i < 5; i++) {
            int idx = tid + i * 256;          // < 1280
            int k = idx / 40;
            int c4 = idx % 40;
            *reinterpret_cast<float4*>(&Bs[k][c4 * 4]) =
                *reinterpret_cast<const float4*>(W + (size_t)(k0 + k) * HID + c4 * 4);
        }
        __syncthreads();
#pragma unroll
        for (int kk = 0; kk < 32; kk++) {
            float4 a0 = *reinterpret_cast<const float4*>(&As[kk][ty * 8]);
            float4 a1 = *reinterpret_cast<const float4*>(&As[kk][ty * 8 + 4]);
            unsigned long long pa[8];
            pa[0] = f2_dup(a0.x); pa[1] = f2_dup(a0.y);
            pa[2] = f2_dup(a0.z); pa[3] = f2_dup(a0.w);
            pa[4] = f2_dup(a1.x); pa[5] = f2_dup(a1.y);
            pa[6] = f2_dup(a1.z); pa[7] = f2_dup(a1.w);
            unsigned long long b[5];
#pragma unroll
            for (int p = 0; p < 5; p++) b[p] = ld2(&Bs[kk][32 * p + 2 * tx]);
#pragma unroll
            for (int q = 0; q < 8; q++)
#pragma unroll
                for (int p = 0; p < 5; p++) acc[q][p] = f2_fma(pa[q], b[p], acc[q][p]);
        }
        __syncthreads();
    }
    // epilogue: scale by inv[row], store
#pragma unroll
    for (int q = 0; q < 8; q++) {
        int gr = rowBase + ty * 8 + q;
        if (gr < M) {
            float s = g_inv[gr];
            float* dstp = g_hs + (size_t)gr * HID;
#pragma unroll
            for (int p = 0; p < 5; p++) {
                F2U t; t.u = acc[q][p];
                t.f2.x *= s; t.f2.y *= s;
                *reinterpret_cast<float2*>(dstp + 32 * p + 2 * tx) = t.f2;
            }
        }
    }
}

// ---------------- Aggregate + bias + BN + ReLU ----------------
// out[d] = relu( BN( inv[d]*(hs[d] + sum_{s in in(d)} hs[s]) + bias ) )
__global__ __launch_bounds__(256) void k_agg(const float* __restrict__ bias,
                                             const float* __restrict__ gam,
                                             const float* __restrict__ bet,
                                             const float* __restrict__ mean,
                                             const float* __restrict__ var) {
    int d = (blockIdx.x * blockDim.x + threadIdx.x) >> 5;
    int lane = threadIdx.x & 31;
    if (d >= NN) return;

    const float* hr = g_hs + (size_t)d * HID;
    unsigned long long acc01 = ld2(hr + 2 * lane);          // self-loop term
    unsigned long long acc23 = ld2(hr + 64 + 2 * lane);
    float acc4 = hr[128 + lane];

    // hoist BN constants (lane covers cols c0,c0+1,c2,c2+1,c4)
    int c0 = 2 * lane, c2 = 64 + 2 * lane, c4 = 128 + lane;
    float idv = g_inv[d];
    float A0 = gam[c0]     * rsqrtf(var[c0]     + BN_EPS);
    float A1 = gam[c0 + 1] * rsqrtf(var[c0 + 1] + BN_EPS);
    float A2 = gam[c2]     * rsqrtf(var[c2]     + BN_EPS);
    float A3 = gam[c2 + 1] * rsqrtf(var[c2 + 1] + BN_EPS);
    float A4 = gam[c4]     * rsqrtf(var[c4]     + BN_EPS);
    float Q0 = (bias[c0]     - mean[c0])     * A0 + bet[c0];
    float Q1 = (bias[c0 + 1] - mean[c0 + 1]) * A1 + bet[c0 + 1];
    float Q2 = (bias[c2]     - mean[c2])     * A2 + bet[c2];
    float Q3 = (bias[c2 + 1] - mean[c2 + 1]) * A3 + bet[c2 + 1];
    float Q4 = (bias[c4]     - mean[c4])     * A4 + bet[c4];

    int beg = g_rowptr[d], end = g_rowptr[d + 1];
    for (int e0 = beg; e0 < end; e0 += 32) {
        int n = min(32, end - e0);
        int myidx = (lane < n) ? g_colidx[e0 + lane] : 0;
        for (int t = 0; t < n; t++) {
            int s = __shfl_sync(0xffffffffu, myidx, t);
            const float* r = g_hs + (size_t)s * HID;
            acc01 = f2_add(acc01, ld2(r + 2 * lane));
            acc23 = f2_add(acc23, ld2(r + 64 + 2 * lane));
            acc4 += r[128 + lane];
        }
    }

    F2U a01, a23; a01.u = acc01; a23.u = acc23;
    float* o = g_feat + (size_t)d * HID;
    F2U y01, y23;
    y01.f2.x = fmaxf(fmaf(a01.f2.x, idv * A0, Q0), 0.f);
    y01.f2.y = fmaxf(fmaf(a01.f2.y, idv * A1, Q1), 0.f);
    y23.f2.x = fmaxf(fmaf(a23.f2.x, idv * A2, Q2), 0.f);
    y23.f2.y = fmaxf(fmaf(a23.f2.y, idv * A3, Q3), 0.f);
    float y4 = fmaxf(fmaf(acc4, idv * A4, Q4), 0.f);
    *reinterpret_cast<float2*>(o + 2 * lane) = y01.f2;
    *reinterpret_cast<float2*>(o + 64 + 2 * lane) = y23.f2;
    o[128 + lane] = y4;
}

// ---------------- mean pool per graph ----------------
__global__ void k_pool() {   // grid: NG blocks x HID threads
    int g = blockIdx.x;
    int c = threadIdx.x;
    int s0 = g_goff[g];
    int cnt = g_goff[g + 1] - s0;
    float s = 0.f;
    for (int i = 0; i < cnt; i++) s += g_feat[(size_t)(s0 + i) * HID + c];
    g_pooled[g * HID + c] = s / fmaxf((float)cnt, 1.f);
}

// ---------------- MLP head ----------------
__global__ void k_head(const float* __restrict__ Wc1, const float* __restrict__ bc1,
                       const float* __restrict__ Wc2, const float* __restrict__ bc2,
                       float* __restrict__ out) {   // grid: NG blocks x 80 threads
    __shared__ float p[HID];
    __shared__ float z[80];
    int g = blockIdx.x;
    int j = threadIdx.x;
    p[j] = g_pooled[g * HID + j];
    p[j + 80] = g_pooled[g * HID + j + 80];
    __syncthreads();
    float s = bc1[j];
    for (int i = 0; i < HID; i++) s = fmaf(p[i], Wc1[i * 80 + j], s);
    z[j] = fmaxf(s, 0.f);
    __syncthreads();
    if (j < NC) {
        float o = bc2[j];
        for (int i = 0; i < 80; i++) o = fmaf(z[i], Wc2[i * NC + j], o);
        out[g * NC + j] = o;
    }
}

// ---------------- launch ----------------
extern "C" void kernel_launch(void* const* d_in, const int* in_sizes, int n_in,
                              void* d_out, int out_size) {
    const float* x   = (const float*)d_in[0];
    const int* ei    = (const int*)d_in[1];
    const int* batch = (const int*)d_in[2];
    const float* W1  = (const float*)d_in[3];
    const float* b1  = (const float*)d_in[4];
    const float* W2  = (const float*)d_in[5];
    const float* b2  = (const float*)d_in[6];
    const float* W3  = (const float*)d_in[7];
    const float* b3  = (const float*)d_in[8];
    const float* g1  = (const float*)d_in[9];
    const float* be1 = (const float*)d_in[10];
    const float* m1  = (const float*)d_in[11];
    const float* v1  = (const float*)d_in[12];
    const float* g2  = (const float*)d_in[13];
    const float* be2 = (const float*)d_in[14];
    const float* m2  = (const float*)d_in[15];
    const float* v2  = (const float*)d_in[16];
    const float* g3  = (const float*)d_in[17];
    const float* be3 = (const float*)d_in[18];
    const float* m3  = (const float*)d_in[19];
    const float* v3  = (const float*)d_in[20];
    const float* Wc1 = (const float*)d_in[21];
    const float* bc1 = (const float*)d_in[22];
    const float* Wc2 = (const float*)d_in[23];
    const float* bc2 = (const float*)d_in[24];
    const int* src = ei;
    const int* dst = ei + NE;
    float* out = (float*)d_out;

    float* feat_ptr = nullptr;
    cudaGetSymbolAddress((void**)&feat_ptr, g_feat);
    void* indeg_ptr = nullptr;
    cudaGetSymbolAddress(&indeg_ptr, g_indeg);
    void* gcnt_ptr = nullptr;
    cudaGetSymbolAddress(&gcnt_ptr, g_gcnt);

    // ---- graph structure (rebuilt each call; deterministic work) ----
    cudaMemsetAsync(indeg_ptr, 0, NN * sizeof(int));
    cudaMemsetAsync(gcnt_ptr, 0, NG * sizeof(int));
    k_count2<<<2048, 256>>>(dst, batch);
    k_scan1<<<(NN + 511) / 512, 512>>>();
    k_scan2g<<<1, 512>>>((NN + 511) / 512);
    k_scan3<<<(NN + 255) / 256, 256>>>();
    k_scatter<<<2048, 256>>>(src, dst);

    const int gemm_blocks = (NN + 127) / 128;
    const int agg_blocks = (NN + 7) / 8;   // 8 warps per 256-thread block

    // layer 1
    k_gemm<<<gemm_blocks, 256>>>(x, W1, NN, FIN);
    k_agg<<<agg_blocks, 256>>>(b1, g1, be1, m1, v1);
    // layer 2
    k_gemm<<<gemm_blocks, 256>>>(feat_ptr, W2, NN, HID);
    k_agg<<<agg_blocks, 256>>>(b2, g2, be2, m2, v2);
    // layer 3
    k_gemm<<<gemm_blocks, 256>>>(feat_ptr, W3, NN, HID);
    k_agg<<<agg_blocks, 256>>>(b3, g3, be3, m3, v3);

    // pool + head
    k_pool<<<NG, HID>>>();
    k_head<<<NG, 80>>>(Wc1, bc1, Wc2, bc2, out);
}